// round 2
// baseline (speedup 1.0000x reference)
#include <cuda_runtime.h>
#include <math.h>

#define BB   4
#define RR   64
#define CC   192
#define WNN  16
#define WSZ  16
#define TAPS 9
#define DT   ((WNN + 1) * CC)   // 3264

// ---------------- device scratch (no allocations allowed) ----------------
__device__ float g_t[BB * WNN];            // pooled+downchannel logits
__device__ float g_w[BB * WNN];            // sigmoid window weights
__device__ float g_wg[BB * WNN];           // w * gk_w
__device__ float g_fwT[DT * CC];           // fusion_w transposed: [d][cout]
__device__ float g_Weff[BB * TAPS * CC * CC]; // [b][tap][c][cout]

// ---------------------------------------------------------------------------
// Kernel A: per (b, window): t[b,win] = dc_b + sum_c dc_w[win,c] * pooled[b,win,c]
// pooled reduced analytically: depthwise-conv-then-mean == sum_{p,q} k[p,q]*S[p,q]/256
// where S[p,q] = window total minus excluded edge row/col (+ corner).
// ---------------------------------------------------------------------------
__global__ void kA(const float* __restrict__ x, const float* __restrict__ k1,
                   const float* __restrict__ dcw, const float* __restrict__ dcb) {
    int b   = blockIdx.x >> 4;
    int win = blockIdx.x & 15;
    int c   = threadIdx.x;            // 0..191
    int rb  = win >> 2, cb = win & 3;
    const float* xp = x + ((size_t)b * RR * RR) * CC + c;
    int base = (rb * WSZ) * RR + cb * WSZ;

    float T = 0.f, r0 = 0.f, r15 = 0.f, c0 = 0.f, c15 = 0.f;
    float e00 = 0.f, e0f = 0.f, ef0 = 0.f, eff = 0.f;
    for (int i = 0; i < 16; i++) {
        float rowacc = 0.f, vj0 = 0.f, vj15 = 0.f;
#pragma unroll
        for (int j = 0; j < 16; j++) {
            float v = xp[(size_t)(base + i * RR + j) * CC];
            rowacc += v;
            if (j == 0)  { c0  += v; vj0  = v; }
            if (j == 15) { c15 += v; vj15 = v; }
        }
        T += rowacc;
        if (i == 0)  { r0  = rowacc; e00 = vj0; e0f = vj15; }
        if (i == 15) { r15 = rowacc; ef0 = vj0; eff = vj15; }
    }

    float Rex[3] = { r15, 0.f, r0 };
    float Cex[3] = { c15, 0.f, c0 };
    const float* kp = k1 + (size_t)(win * CC + c) * TAPS;
    float pooled = 0.f;
#pragma unroll
    for (int p = 0; p < 3; p++) {
#pragma unroll
        for (int q = 0; q < 3; q++) {
            float corner = 0.f;
            if (p == 0 && q == 0) corner = eff;
            if (p == 0 && q == 2) corner = ef0;
            if (p == 2 && q == 0) corner = e0f;
            if (p == 2 && q == 2) corner = e00;
            float S = T - Rex[p] - Cex[q] + corner;
            pooled += kp[p * 3 + q] * S;
        }
    }
    pooled *= (1.f / 256.f);
    float contrib = pooled * dcw[win * CC + c];

    __shared__ float red[192];
    red[c] = contrib;
    __syncthreads();
    for (int s = 96; s >= 6; s >>= 1) {
        if (c < s) red[c] += red[c + s];
        __syncthreads();
    }
    if (c == 0) {
        float tot = red[0] + red[1] + red[2] + red[3] + red[4] + red[5];
        g_t[b * WNN + win] = tot + dcb[win];
    }
}

// ---------------------------------------------------------------------------
// Kernel B: tiny MLP. h = gelu(t @ l1^T + b1); w = sigmoid(h @ l2^T + b2)
// ---------------------------------------------------------------------------
__global__ void kB(const float* __restrict__ l1w, const float* __restrict__ l1b,
                   const float* __restrict__ l2w, const float* __restrict__ l2b,
                   const float* __restrict__ gkw) {
    __shared__ float ts[BB * WNN];
    __shared__ float hs[BB * 64];
    int tid = threadIdx.x;
    if (tid < BB * WNN) ts[tid] = g_t[tid];
    __syncthreads();
    {
        int b = tid >> 6, j = tid & 63;
        float a = l1b[j];
#pragma unroll
        for (int s = 0; s < 16; s++) a += ts[b * 16 + s] * l1w[j * 16 + s];
        hs[tid] = 0.5f * a * (1.f + erff(a * 0.70710678118654752f)); // exact gelu
    }
    __syncthreads();
    if (tid < BB * WNN) {
        int b = tid >> 4, s = tid & 15;
        float a = l2b[s];
#pragma unroll
        for (int j = 0; j < 64; j++) a += hs[b * 64 + j] * l2w[s * 64 + j];
        float wv = 1.f / (1.f + expf(-a));
        g_w[tid]  = wv;
        g_wg[tid] = wv * gkw[s];
    }
}

// ---------------------------------------------------------------------------
// Kernel C0: transpose fusion_w (cout-major -> d-major) for coalesced use in kC.
// ---------------------------------------------------------------------------
__global__ void kC0(const float* __restrict__ fw) {
    int idx = blockIdx.x * blockDim.x + threadIdx.x;
    if (idx >= DT * CC) return;
    int cout = idx % CC;
    int d    = idx / CC;
    g_fwT[idx] = fw[(size_t)cout * DT + d];
}

// ---------------------------------------------------------------------------
// Kernel C: W_eff[b,tap,c,cout] = sum_{s=0..16} allk[b,s,c,tap] * fwT[s*C+c][cout]
// allk (s<16) = w[b,s]*conv1_w[s,c,tap]; allk[16] = sum_s wg[b,s]*conv1_w + gk_b.
// One block per (b,tap,c), 192 threads = cout.
// ---------------------------------------------------------------------------
__global__ void kC(const float* __restrict__ k1, const float* __restrict__ gkb) {
    int bid = blockIdx.x;
    int c   = bid % CC;
    int tap = (bid / CC) % TAPS;
    int b   = bid / (CC * TAPS);
    __shared__ float ak[17];
    int tid = threadIdx.x;
    if (tid < 16)
        ak[tid] = g_w[b * 16 + tid] * k1[(size_t)(tid * CC + c) * TAPS + tap];
    if (tid == 16) {
        float s = gkb[0];
        for (int u = 0; u < 16; u++)
            s += g_wg[b * 16 + u] * k1[(size_t)(u * CC + c) * TAPS + tap];
        ak[16] = s;
    }
    __syncthreads();
    float acc = 0.f;
#pragma unroll
    for (int s = 0; s < 17; s++)
        acc += ak[s] * g_fwT[(size_t)(s * CC + c) * CC + tid];
    g_Weff[(((size_t)b * TAPS + tap) * CC + c) * CC + tid] = acc;
}

// ---------------------------------------------------------------------------
// Kernel D: per-sample dense 3x3 conv 192->192 on 64x64 (implicit GEMM, fp32 SIMT)
// Block: 8x8 pixel tile x 192 couts. 256 threads, thread tile 4px x 12cout.
// smem: x patch 10x10x192 (76.8KB) + W chunk 8c x 9tap x 192cout (55KB).
// Epilogue adds fusion_b and writes channels-last output.
// ---------------------------------------------------------------------------
__global__ void __launch_bounds__(256)
kD(const float* __restrict__ x, const float* __restrict__ fb, float* __restrict__ out) {
    extern __shared__ float sm[];
    float* xs = sm;            // [c][100]  (pixel = yy*10+xx)
    float* ws = sm + 19200;    // [cl][tap][cout]

    int b   = blockIdx.z;
    int by0 = blockIdx.y * 8;
    int bx0 = blockIdx.x * 8;
    int tid = threadIdx.x;

    // ---- stage x patch (with zero padding) ----
    const float* xb = x + (size_t)b * RR * RR * CC;
    for (int i = tid; i < 4800; i += 256) {
        int pix = i / 48, c4 = i % 48;
        int yy = pix / 10, xx = pix % 10;
        int gy = by0 - 1 + yy, gx = bx0 - 1 + xx;
        float4 v = make_float4(0.f, 0.f, 0.f, 0.f);
        if (gy >= 0 && gy < RR && gx >= 0 && gx < RR)
            v = *(const float4*)(xb + (size_t)(gy * RR + gx) * CC + c4 * 4);
        xs[(c4 * 4 + 0) * 100 + pix] = v.x;
        xs[(c4 * 4 + 1) * 100 + pix] = v.y;
        xs[(c4 * 4 + 2) * 100 + pix] = v.z;
        xs[(c4 * 4 + 3) * 100 + pix] = v.w;
    }

    int cg  = tid & 15;          // cout group: couts [cg*12, cg*12+12)
    int pg  = tid >> 4;          // pixel group
    int py  = pg >> 1;           // row in tile 0..7
    int gx4 = (pg & 1) * 4;      // col base 0 or 4

    float acc[4][12];
#pragma unroll
    for (int k = 0; k < 4; k++)
#pragma unroll
        for (int j = 0; j < 12; j++) acc[k][j] = 0.f;

    const float* Wb = g_Weff + (size_t)b * TAPS * CC * CC;

#pragma unroll 1
    for (int cc = 0; cc < CC; cc += 8) {
        __syncthreads();   // previous compute done (and xs staged, first iter)
        // stage W chunk: layout matches linear index (cl, tap, cout)
        for (int i = tid; i < 13824; i += 256) {
            int cout = i % 192;
            int r    = i / 192;
            int tap  = r % 9;
            int cl   = r / 9;
            ws[i] = Wb[((size_t)tap * CC + (cc + cl)) * CC + cout];
        }
        __syncthreads();

#pragma unroll 1
        for (int cl = 0; cl < 8; cl++) {
            const float* xrow = xs + (cc + cl) * 100;
            const float* wrow = ws + cl * 9 * 192;
#pragma unroll
            for (int t = 0; t < 9; t++) {
                int ty = t / 3, tx = t % 3;
                const float* wp = wrow + t * 192 + cg * 12;
                float wv[12];
#pragma unroll
                for (int j4 = 0; j4 < 3; j4++) {
                    float4 t4 = *(const float4*)(wp + 4 * j4);
                    wv[4 * j4 + 0] = t4.x; wv[4 * j4 + 1] = t4.y;
                    wv[4 * j4 + 2] = t4.z; wv[4 * j4 + 3] = t4.w;
                }
                const float* xp2 = xrow + (py + ty) * 10 + gx4 + tx;
#pragma unroll
                for (int k = 0; k < 4; k++) {
                    float xv = xp2[k];
#pragma unroll
                    for (int j = 0; j < 12; j++)
                        acc[k][j] = fmaf(xv, wv[j], acc[k][j]);
                }
            }
        }
    }

    // ---- epilogue: + fusion_b, store channels-last ----
    float fbv[12];
#pragma unroll
    for (int j4 = 0; j4 < 3; j4++) {
        float4 t4 = *(const float4*)(fb + cg * 12 + 4 * j4);
        fbv[4 * j4 + 0] = t4.x; fbv[4 * j4 + 1] = t4.y;
        fbv[4 * j4 + 2] = t4.z; fbv[4 * j4 + 3] = t4.w;
    }
#pragma unroll
    for (int k = 0; k < 4; k++) {
        size_t o = (((size_t)b * RR * RR) + (size_t)(by0 + py) * RR + (bx0 + gx4 + k)) * CC
                   + cg * 12;
#pragma unroll
        for (int j4 = 0; j4 < 3; j4++) {
            float4 v;
            v.x = acc[k][4 * j4 + 0] + fbv[4 * j4 + 0];
            v.y = acc[k][4 * j4 + 1] + fbv[4 * j4 + 1];
            v.z = acc[k][4 * j4 + 2] + fbv[4 * j4 + 2];
            v.w = acc[k][4 * j4 + 3] + fbv[4 * j4 + 3];
            *(float4*)(out + o + 4 * j4) = v;
        }
    }
}

// ---------------------------------------------------------------------------
extern "C" void kernel_launch(void* const* d_in, const int* in_sizes, int n_in,
                              void* d_out, int out_size) {
    const float* x   = (const float*)d_in[0];
    const float* k1  = (const float*)d_in[1];   // conv1_w (3072,1,3,3)
    const float* dcw = (const float*)d_in[2];
    const float* dcb = (const float*)d_in[3];
    const float* l1w = (const float*)d_in[4];
    const float* l1b = (const float*)d_in[5];
    const float* l2w = (const float*)d_in[6];
    const float* l2b = (const float*)d_in[7];
    const float* gkw = (const float*)d_in[8];
    const float* gkb = (const float*)d_in[9];
    const float* fw  = (const float*)d_in[10];
    const float* fb  = (const float*)d_in[11];
    float* out = (float*)d_out;

    cudaFuncSetAttribute(kD, cudaFuncAttributeMaxDynamicSharedMemorySize, 132096);

    kA<<<BB * WNN, CC>>>(x, k1, dcw, dcb);
    kB<<<1, 256>>>(l1w, l1b, l2w, l2b, gkw);
    kC0<<<(DT * CC + 255) / 256, 256>>>(fw);
    kC<<<BB * TAPS * CC, CC>>>(k1, gkb);
    dim3 g(8, 8, BB);
    kD<<<g, 256, 132096>>>(x, fb, out);
}

// round 4
// speedup vs baseline: 2.4133x; 2.4133x over previous
#include <cuda_runtime.h>
#include <math.h>
#include <cstdint>

#define BB   4
#define RR   64
#define CC   192
#define WNN  16
#define WSZ  16
#define TAPS 9

// ---------------- device scratch ----------------
__device__ float g_t[BB * WNN];
__device__ float g_w[BB * WNN];
__device__ float g_wg[BB * WNN];
__device__ float g_WeffT[BB * TAPS * CC * CC];   // [b][tap][cout][c], tf32-rounded

__device__ __forceinline__ uint32_t f2tf(float f) {
    uint32_t u; asm("cvt.rna.tf32.f32 %0, %1;" : "=r"(u) : "f"(f)); return u;
}

__device__ __forceinline__ void mma_tf32(float* d, const uint32_t* a, const uint32_t* b) {
    asm volatile(
        "mma.sync.aligned.m16n8k8.row.col.f32.tf32.tf32.f32 "
        "{%0,%1,%2,%3}, {%4,%5,%6,%7}, {%8,%9}, {%0,%1,%2,%3};"
        : "+f"(d[0]), "+f"(d[1]), "+f"(d[2]), "+f"(d[3])
        : "r"(a[0]), "r"(a[1]), "r"(a[2]), "r"(a[3]), "r"(b[0]), "r"(b[1]));
}

// ---------------------------------------------------------------------------
// Kernel A: pooled depthwise stats -> downchannel logits (validated)
// ---------------------------------------------------------------------------
__global__ void kA(const float* __restrict__ x, const float* __restrict__ k1,
                   const float* __restrict__ dcw, const float* __restrict__ dcb) {
    int b   = blockIdx.x >> 4;
    int win = blockIdx.x & 15;
    int c   = threadIdx.x;
    int rb  = win >> 2, cb = win & 3;
    const float* xp = x + ((size_t)b * RR * RR) * CC + c;
    int base = (rb * WSZ) * RR + cb * WSZ;

    float T = 0.f, r0 = 0.f, r15 = 0.f, c0 = 0.f, c15 = 0.f;
    float e00 = 0.f, e0f = 0.f, ef0 = 0.f, eff = 0.f;
    for (int i = 0; i < 16; i++) {
        float rowacc = 0.f, vj0 = 0.f, vj15 = 0.f;
#pragma unroll
        for (int j = 0; j < 16; j++) {
            float v = xp[(size_t)(base + i * RR + j) * CC];
            rowacc += v;
            if (j == 0)  { c0  += v; vj0  = v; }
            if (j == 15) { c15 += v; vj15 = v; }
        }
        T += rowacc;
        if (i == 0)  { r0  = rowacc; e00 = vj0; e0f = vj15; }
        if (i == 15) { r15 = rowacc; ef0 = vj0; eff = vj15; }
    }

    float Rex[3] = { r15, 0.f, r0 };
    float Cex[3] = { c15, 0.f, c0 };
    const float* kp = k1 + (size_t)(win * CC + c) * TAPS;
    float pooled = 0.f;
#pragma unroll
    for (int p = 0; p < 3; p++) {
#pragma unroll
        for (int q = 0; q < 3; q++) {
            float corner = 0.f;
            if (p == 0 && q == 0) corner = eff;
            if (p == 0 && q == 2) corner = ef0;
            if (p == 2 && q == 0) corner = e0f;
            if (p == 2 && q == 2) corner = e00;
            float S = T - Rex[p] - Cex[q] + corner;
            pooled += kp[p * 3 + q] * S;
        }
    }
    pooled *= (1.f / 256.f);
    float contrib = pooled * dcw[win * CC + c];

    __shared__ float red[192];
    red[c] = contrib;
    __syncthreads();
    for (int s = 96; s >= 6; s >>= 1) {
        if (c < s) red[c] += red[c + s];
        __syncthreads();
    }
    if (c == 0) {
        float tot = red[0] + red[1] + red[2] + red[3] + red[4] + red[5];
        g_t[b * WNN + win] = tot + dcb[win];
    }
}

// ---------------------------------------------------------------------------
// Kernel B: tiny MLP (validated)
// ---------------------------------------------------------------------------
__global__ void kB(const float* __restrict__ l1w, const float* __restrict__ l1b,
                   const float* __restrict__ l2w, const float* __restrict__ l2b,
                   const float* __restrict__ gkw) {
    __shared__ float ts[BB * WNN];
    __shared__ float hs[BB * 64];
    int tid = threadIdx.x;
    if (tid < BB * WNN) ts[tid] = g_t[tid];
    __syncthreads();
    {
        int b = tid >> 6, j = tid & 63;
        float a = l1b[j];
#pragma unroll
        for (int s = 0; s < 16; s++) a += ts[b * 16 + s] * l1w[j * 16 + s];
        hs[tid] = 0.5f * a * (1.f + erff(a * 0.70710678118654752f));
    }
    __syncthreads();
    if (tid < BB * WNN) {
        int b = tid >> 4, s = tid & 15;
        float a = l2b[s];
#pragma unroll
        for (int j = 0; j < 64; j++) a += hs[b * 64 + j] * l2w[s * 64 + j];
        float wv = 1.f / (1.f + expf(-a));
        g_w[tid]  = wv;
        g_wg[tid] = wv * gkw[s];
    }
}

// ---------------------------------------------------------------------------
// Kernel W: WeffT[b][tap][cout][c] (tf32-pre-rounded). fw read once chip-wide.
// ---------------------------------------------------------------------------
__global__ void __launch_bounds__(192)
kW(const float* __restrict__ k1, const float* __restrict__ gkb,
   const float* __restrict__ fw) {
    int cout = blockIdx.x;
    int c    = threadIdx.x;
    __shared__ float sw_[64], swg[64];
    if (c < 64) { sw_[c] = g_w[c]; swg[c] = g_wg[c]; }
    __syncthreads();

    float f[17];
    const float* fp = fw + (size_t)cout * ((WNN + 1) * CC) + c;
#pragma unroll
    for (int s = 0; s < 17; s++) f[s] = fp[s * CC];
    float g0 = gkb[0];

#pragma unroll 1
    for (int tap = 0; tap < 9; tap++) {
        float kv[16];
#pragma unroll
        for (int s = 0; s < 16; s++)
            kv[s] = k1[((size_t)(s * CC + c)) * TAPS + tap];
#pragma unroll
        for (int b = 0; b < 4; b++) {
            float acc = 0.f, ga = g0;
#pragma unroll
            for (int s = 0; s < 16; s++) {
                acc = fmaf(sw_[b * 16 + s] * kv[s], f[s], acc);
                ga  = fmaf(swg[b * 16 + s], kv[s], ga);
            }
            acc = fmaf(ga, f[16], acc);
            g_WeffT[(((size_t)(b * TAPS + tap)) * CC + cout) * CC + c] =
                __uint_as_float(f2tf(acc));
        }
    }
}

// ---------------------------------------------------------------------------
// Kernel D: tf32 mma.sync implicit-GEMM conv.
// CTA: M=128 pixels x N=192 couts. K=1728 in 54 chunks of 32 (tap-aligned).
// Smem holds fragments in mma lane order; double-buffered; LDG prefetch.
// ---------------------------------------------------------------------------
#define ABUF_W 4096          // 128m x 32k words
#define BBUF_W 6144          // 32k x 192n words
#define BUF_W  (ABUF_W + BBUF_W)

__global__ void __launch_bounds__(256)
kD(const float* __restrict__ x, const float* __restrict__ fb,
   float* __restrict__ out) {
    extern __shared__ float sm[];
    int tid  = threadIdx.x;
    int lane = tid & 31;
    int wid  = tid >> 5;
    int b    = blockIdx.y;
    int mt   = blockIdx.x;                    // pixels [mt*128, mt*128+128)

    const float* xb = x + (size_t)b * RR * RR * CC;
    const float* Wb = g_WeffT + (size_t)b * TAPS * CC * CC;

    int wm = (wid >> 2) * 4;                  // mtile base (0 or 4)
    int wn = (wid & 3) * 6;                   // ntile base (0,6,12,18)

    float acc[4][6][4];
#pragma unroll
    for (int mi = 0; mi < 4; mi++)
#pragma unroll
        for (int ni = 0; ni < 6; ni++)
#pragma unroll
            for (int r = 0; r < 4; r++) acc[mi][ni][r] = 0.f;

    float4 av[4], bv[6];

    // ---- gmem fetch of one K-chunk into regs ----
    auto fetch = [&](int kc) {
        int tap = kc / 6;
        int cbs = (kc - tap * 6) * 32;
        int dy = tap / 3 - 1, dx = tap % 3 - 1;
#pragma unroll
        for (int j = 0; j < 4; j++) {
            int i = tid + 256 * j;
            int m = i >> 3, f = i & 7;
            int py = mt * 2 + (m >> 6), px = m & 63;
            int sy = py + dy, sx = px + dx;
            if ((unsigned)sy < RR && (unsigned)sx < RR)
                av[j] = *(const float4*)(xb + ((size_t)(sy * RR + sx)) * CC + cbs + f * 4);
            else
                av[j] = make_float4(0.f, 0.f, 0.f, 0.f);
        }
#pragma unroll
        for (int j = 0; j < 6; j++) {
            int i = tid + 256 * j;
            int n = i >> 3, f = i & 7;
            bv[j] = *(const float4*)(Wb + ((size_t)tap * CC + n) * CC + cbs + f * 4);
        }
    };

    // ---- STS regs -> fragment-ordered smem buffer ----
    auto store = [&](float* buf) {
        float* bufB = buf + ABUF_W;
#pragma unroll
        for (int j = 0; j < 4; j++) {
            int i = tid + 256 * j;
            int m = i >> 3, f = i & 7;
            int q  = ((m >> 4) << 2) + (f >> 1);
            int rb = ((f & 1) << 1) | ((m >> 3) & 1);
            float* p = buf + q * 128 + (m & 7) * 16 + rb;
            p[0]  = __uint_as_float(f2tf(av[j].x));
            p[4]  = __uint_as_float(f2tf(av[j].y));
            p[8]  = __uint_as_float(f2tf(av[j].z));
            p[12] = __uint_as_float(f2tf(av[j].w));
        }
#pragma unroll
        for (int j = 0; j < 6; j++) {
            int i = tid + 256 * j;
            int n = i >> 3, f = i & 7;
            int q  = ((n >> 3) << 2) + (f >> 1);
            int rb = f & 1;
            float* p = bufB + q * 64 + (n & 7) * 8 + rb;
            p[0] = bv[j].x;  p[2] = bv[j].y;  p[4] = bv[j].z;  p[6] = bv[j].w;
        }
    };

    fetch(0);
    store(sm);
    __syncthreads();

#pragma unroll 1
    for (int kc = 0; kc < 54; kc++) {
        if (kc < 53) fetch(kc + 1);

        const float* bufA = sm + (kc & 1) * BUF_W;
        const float* bufB = bufA + ABUF_W;
#pragma unroll
        for (int ks = 0; ks < 4; ks++) {
            uint32_t af[4][4], bf[6][2];
#pragma unroll
            for (int mi = 0; mi < 4; mi++) {
                float4 v = *(const float4*)(bufA + ((wm + mi) * 4 + ks) * 128 + lane * 4);
                af[mi][0] = __float_as_uint(v.x);
                af[mi][1] = __float_as_uint(v.y);
                af[mi][2] = __float_as_uint(v.z);
                af[mi][3] = __float_as_uint(v.w);
            }
#pragma unroll
            for (int ni = 0; ni < 6; ni++) {
                float2 v = *(const float2*)(bufB + ((wn + ni) * 4 + ks) * 64 + lane * 2);
                bf[ni][0] = __float_as_uint(v.x);
                bf[ni][1] = __float_as_uint(v.y);
            }
#pragma unroll
            for (int mi = 0; mi < 4; mi++)
#pragma unroll
                for (int ni = 0; ni < 6; ni++)
                    mma_tf32(acc[mi][ni], af[mi], bf[ni]);
        }
        __syncthreads();
        if (kc < 53) store(sm + ((kc + 1) & 1) * BUF_W);
        __syncthreads();
    }

    // ---- epilogue: +bias, direct STG.64 ----
#pragma unroll
    for (int ni = 0; ni < 6; ni++) {
        int co = (wid & 3) * 48 + ni * 8 + (lane & 3) * 2;
        float bx = fb[co], by = fb[co + 1];
#pragma unroll
        for (int mi = 0; mi < 4; mi++) {
            int m0 = mt * 128 + (wm + mi) * 16 + (lane >> 2);
            size_t o0 = ((size_t)b * RR * RR + m0) * CC + co;
            float2 v0 = make_float2(acc[mi][ni][0] + bx, acc[mi][ni][1] + by);
            float2 v1 = make_float2(acc[mi][ni][2] + bx, acc[mi][ni][3] + by);
            *(float2*)(out + o0) = v0;
            *(float2*)(out + o0 + (size_t)8 * CC) = v1;
        }
    }
}

// ---------------------------------------------------------------------------
extern "C" void kernel_launch(void* const* d_in, const int* in_sizes, int n_in,
                              void* d_out, int out_size) {
    const float* x   = (const float*)d_in[0];
    const float* k1  = (const float*)d_in[1];
    const float* dcw = (const float*)d_in[2];
    const float* dcb = (const float*)d_in[3];
    const float* l1w = (const float*)d_in[4];
    const float* l1b = (const float*)d_in[5];
    const float* l2w = (const float*)d_in[6];
    const float* l2b = (const float*)d_in[7];
    const float* gkw = (const float*)d_in[8];
    const float* gkb = (const float*)d_in[9];
    const float* fw  = (const float*)d_in[10];
    const float* fb  = (const float*)d_in[11];
    float* out = (float*)d_out;

    cudaFuncSetAttribute(kD, cudaFuncAttributeMaxDynamicSharedMemorySize,
                         2 * BUF_W * sizeof(float));

    kA<<<BB * WNN, CC>>>(x, k1, dcw, dcb);
    kB<<<1, 256>>>(l1w, l1b, l2w, l2b, gkw);
    kW<<<CC, CC>>>(k1, gkb, fw);
    dim3 g(32, BB);
    kD<<<g, 256, 2 * BUF_W * sizeof(float)>>>(x, fb, out);
}

// round 5
// speedup vs baseline: 4.7309x; 1.9604x over previous
#include <cuda_runtime.h>
#include <math.h>
#include <cstdint>

#define BB   4
#define RR   64
#define CC   192
#define WNN  16
#define WSZ  16
#define TAPS 9

// ---------------- device scratch ----------------
__device__ float g_t[BB * WNN];
__device__ float g_w[BB * WNN];
__device__ float g_wg[BB * WNN];
// B operand in mma-fragment order: [b][tap][cg][6144 words]
__device__ float g_WeffB[BB * TAPS * 6 * 6144];

__device__ __forceinline__ uint32_t f2tf(float f) {
    uint32_t u; asm("cvt.rna.tf32.f32 %0, %1;" : "=r"(u) : "f"(f)); return u;
}
__device__ __forceinline__ uint32_t smem_u32(const void* p) {
    uint32_t a;
    asm("{ .reg .u64 t; cvta.to.shared.u64 t, %1; cvt.u32.u64 %0, t; }"
        : "=r"(a) : "l"(p));
    return a;
}
__device__ __forceinline__ void mma_tf32(float* d, const uint32_t* a, const uint32_t* b) {
    asm volatile(
        "mma.sync.aligned.m16n8k8.row.col.f32.tf32.tf32.f32 "
        "{%0,%1,%2,%3}, {%4,%5,%6,%7}, {%8,%9}, {%0,%1,%2,%3};"
        : "+f"(d[0]), "+f"(d[1]), "+f"(d[2]), "+f"(d[3])
        : "r"(a[0]), "r"(a[1]), "r"(a[2]), "r"(a[3]), "r"(b[0]), "r"(b[1]));
}
#define CP_ASYNC16(dst, src) \
    asm volatile("cp.async.ca.shared.global [%0], [%1], 16;" :: "r"(dst), "l"(src))
#define CP_COMMIT() asm volatile("cp.async.commit_group;" ::: "memory")
#define CP_WAIT(n)  asm volatile("cp.async.wait_group %0;" :: "n"(n) : "memory")

// ---------------------------------------------------------------------------
// Kernel A: pooled depthwise stats -> downchannel logits (validated)
// ---------------------------------------------------------------------------
__global__ void kA(const float* __restrict__ x, const float* __restrict__ k1,
                   const float* __restrict__ dcw, const float* __restrict__ dcb) {
    int b   = blockIdx.x >> 4;
    int win = blockIdx.x & 15;
    int c   = threadIdx.x;
    int rb  = win >> 2, cb = win & 3;
    const float* xp = x + ((size_t)b * RR * RR) * CC + c;
    int base = (rb * WSZ) * RR + cb * WSZ;

    float T = 0.f, r0 = 0.f, r15 = 0.f, c0 = 0.f, c15 = 0.f;
    float e00 = 0.f, e0f = 0.f, ef0 = 0.f, eff = 0.f;
    for (int i = 0; i < 16; i++) {
        float rowacc = 0.f, vj0 = 0.f, vj15 = 0.f;
#pragma unroll
        for (int j = 0; j < 16; j++) {
            float v = xp[(size_t)(base + i * RR + j) * CC];
            rowacc += v;
            if (j == 0)  { c0  += v; vj0  = v; }
            if (j == 15) { c15 += v; vj15 = v; }
        }
        T += rowacc;
        if (i == 0)  { r0  = rowacc; e00 = vj0; e0f = vj15; }
        if (i == 15) { r15 = rowacc; ef0 = vj0; eff = vj15; }
    }

    float Rex[3] = { r15, 0.f, r0 };
    float Cex[3] = { c15, 0.f, c0 };
    const float* kp = k1 + (size_t)(win * CC + c) * TAPS;
    float pooled = 0.f;
#pragma unroll
    for (int p = 0; p < 3; p++) {
#pragma unroll
        for (int q = 0; q < 3; q++) {
            float corner = 0.f;
            if (p == 0 && q == 0) corner = eff;
            if (p == 0 && q == 2) corner = ef0;
            if (p == 2 && q == 0) corner = e0f;
            if (p == 2 && q == 2) corner = e00;
            float S = T - Rex[p] - Cex[q] + corner;
            pooled += kp[p * 3 + q] * S;
        }
    }
    pooled *= (1.f / 256.f);
    float contrib = pooled * dcw[win * CC + c];

    __shared__ float red[192];
    red[c] = contrib;
    __syncthreads();
    for (int s = 96; s >= 6; s >>= 1) {
        if (c < s) red[c] += red[c + s];
        __syncthreads();
    }
    if (c == 0) {
        float tot = red[0] + red[1] + red[2] + red[3] + red[4] + red[5];
        g_t[b * WNN + win] = tot + dcb[win];
    }
}

// ---------------------------------------------------------------------------
// Kernel B: tiny MLP (validated)
// ---------------------------------------------------------------------------
__global__ void kB(const float* __restrict__ l1w, const float* __restrict__ l1b,
                   const float* __restrict__ l2w, const float* __restrict__ l2b,
                   const float* __restrict__ gkw) {
    __shared__ float ts[BB * WNN];
    __shared__ float hs[BB * 64];
    int tid = threadIdx.x;
    if (tid < BB * WNN) ts[tid] = g_t[tid];
    __syncthreads();
    {
        int b = tid >> 6, j = tid & 63;
        float a = l1b[j];
#pragma unroll
        for (int s = 0; s < 16; s++) a += ts[b * 16 + s] * l1w[j * 16 + s];
        hs[tid] = 0.5f * a * (1.f + erff(a * 0.70710678118654752f));
    }
    __syncthreads();
    if (tid < BB * WNN) {
        int b = tid >> 4, s = tid & 15;
        float a = l2b[s];
#pragma unroll
        for (int j = 0; j < 64; j++) a += hs[b * 64 + j] * l2w[s * 64 + j];
        float wv = 1.f / (1.f + expf(-a));
        g_w[tid]  = wv;
        g_wg[tid] = wv * gkw[s];
    }
}

// ---------------------------------------------------------------------------
// Kernel W: Weff in mma B-fragment order, tf32-pre-rounded.
// g_WeffB word (per b,tap,cg chunk of 6144):
//   ((n>>3)*4 + (k32>>3))*64 + (n&7)*8 + (k32&3)*2 + ((k32>>2)&1)
// ---------------------------------------------------------------------------
__global__ void __launch_bounds__(192)
kW(const float* __restrict__ k1, const float* __restrict__ gkb,
   const float* __restrict__ fw) {
    int n = blockIdx.x;          // cout
    int c = threadIdx.x;         // cin = k
    __shared__ float sw_[64], swg[64];
    if (c < 64) { sw_[c] = g_w[c]; swg[c] = g_wg[c]; }
    __syncthreads();

    float f[17];
    const float* fp = fw + (size_t)n * ((WNN + 1) * CC) + c;
#pragma unroll
    for (int s = 0; s < 17; s++) f[s] = fp[s * CC];
    float g0 = gkb[0];

    int cg  = c >> 5, k32 = c & 31;
    int wrd = ((n >> 3) * 4 + (k32 >> 3)) * 64 + (n & 7) * 8 +
              (k32 & 3) * 2 + ((k32 >> 2) & 1);

#pragma unroll 1
    for (int tap = 0; tap < 9; tap++) {
        float kv[16];
#pragma unroll
        for (int s = 0; s < 16; s++)
            kv[s] = k1[((size_t)(s * CC + c)) * TAPS + tap];
#pragma unroll
        for (int b = 0; b < 4; b++) {
            float acc = 0.f, ga = g0;
#pragma unroll
            for (int s = 0; s < 16; s++) {
                acc = fmaf(sw_[b * 16 + s] * kv[s], f[s], acc);
                ga  = fmaf(swg[b * 16 + s], kv[s], ga);
            }
            acc = fmaf(ga, f[16], acc);
            g_WeffB[((size_t)(b * 9 + tap) * 6 + cg) * 6144 + wrd] =
                __uint_as_float(f2tf(acc));
        }
    }
}

// ---------------------------------------------------------------------------
// Kernel D: tf32 mma.sync implicit GEMM. CTA: M=64 (one image row) x N=192.
// K = 54 chunks of 32. B via cp.async (triple buf), A via LDG+STS (double buf).
// One __syncthreads per chunk. 2 CTAs/SM.
// ---------------------------------------------------------------------------
#define ABUF_W 2048
#define BBUF_W 6144
#define SMEM_WORDS (2 * ABUF_W + 3 * BBUF_W)   // 22528 words = 90112 B

__global__ void __launch_bounds__(256, 2)
kD(const float* __restrict__ x, const float* __restrict__ fb,
   float* __restrict__ out) {
    extern __shared__ float sm[];
    float* smA = sm;                 // 2 x 2048
    float* smB = sm + 2 * ABUF_W;    // 3 x 6144

    int tid  = threadIdx.x;
    int lane = tid & 31;
    int wid  = tid >> 5;
    int b    = blockIdx.y;
    int mt   = blockIdx.x;           // image row (py), pixels [mt*64, mt*64+64)

    const float* xb = x + (size_t)b * RR * RR * CC;
    const float* WB = g_WeffB + (size_t)b * TAPS * 6 * 6144;

    int wm = (wid >> 2) * 2;         // mtile base (0 or 2)
    int wn = (wid & 3) * 6;          // ntile base

    float acc[2][6][4];
#pragma unroll
    for (int mi = 0; mi < 2; mi++)
#pragma unroll
        for (int ni = 0; ni < 6; ni++)
#pragma unroll
            for (int r = 0; r < 4; r++) acc[mi][ni][r] = 0.f;

    float4 av[2];

    auto stageB = [&](int kc, float* dst) {
        int tap = kc / 6, cg = kc - tap * 6;
        const float* src = WB + ((size_t)tap * 6 + cg) * 6144;
        uint32_t d0 = smem_u32(dst);
#pragma unroll
        for (int j = 0; j < 6; j++) {
            int i = tid + 256 * j;
            CP_ASYNC16(d0 + i * 16, src + i * 4);
        }
    };
    auto fetchA = [&](int kc) {
        int tap = kc / 6;
        int cbs = (kc - tap * 6) * 32;
        int dy = tap / 3 - 1, dx = tap % 3 - 1;
        int sy = mt + dy;
#pragma unroll
        for (int j = 0; j < 2; j++) {
            int i = tid + 256 * j;
            int m = i >> 3, f = i & 7;
            int sx = m + dx;
            if ((unsigned)sy < RR && (unsigned)sx < RR)
                av[j] = *(const float4*)(xb + ((size_t)(sy * RR + sx)) * CC + cbs + f * 4);
            else
                av[j] = make_float4(0.f, 0.f, 0.f, 0.f);
        }
    };
    auto storeA = [&](float* buf) {
#pragma unroll
        for (int j = 0; j < 2; j++) {
            int i = tid + 256 * j;
            int m = i >> 3, f = i & 7;
            int q  = ((m >> 4) << 2) + (f >> 1);
            int rb = ((f & 1) << 1) | ((m >> 3) & 1);
            float* p = buf + q * 128 + (m & 7) * 16 + rb;
            p[0]  = __uint_as_float(f2tf(av[j].x));
            p[4]  = __uint_as_float(f2tf(av[j].y));
            p[8]  = __uint_as_float(f2tf(av[j].z));
            p[12] = __uint_as_float(f2tf(av[j].w));
        }
    };

    // ---- prologue ----
    stageB(0, smB);            CP_COMMIT();
    stageB(1, smB + BBUF_W);   CP_COMMIT();
    fetchA(0);
    storeA(smA);

#pragma unroll 1
    for (int kc = 0; kc < 54; kc++) {
        if (kc < 53) CP_WAIT(1); else CP_WAIT(0);
        __syncthreads();
        if (kc + 2 <= 53) { stageB(kc + 2, smB + ((kc + 2) % 3) * BBUF_W); CP_COMMIT(); }
        if (kc + 1 <= 53) fetchA(kc + 1);

        const float* bufA = smA + (kc & 1) * ABUF_W;
        const float* bufB = smB + (kc % 3) * BBUF_W;
#pragma unroll
        for (int ks = 0; ks < 4; ks++) {
            uint32_t af[2][4], bf[6][2];
#pragma unroll
            for (int mi = 0; mi < 2; mi++) {
                float4 v = *(const float4*)(bufA + ((wm + mi) * 4 + ks) * 128 + lane * 4);
                af[mi][0] = __float_as_uint(v.x);
                af[mi][1] = __float_as_uint(v.y);
                af[mi][2] = __float_as_uint(v.z);
                af[mi][3] = __float_as_uint(v.w);
            }
#pragma unroll
            for (int ni = 0; ni < 6; ni++) {
                float2 v = *(const float2*)(bufB + ((wn + ni) * 4 + ks) * 64 + lane * 2);
                bf[ni][0] = __float_as_uint(v.x);
                bf[ni][1] = __float_as_uint(v.y);
            }
#pragma unroll
            for (int mi = 0; mi < 2; mi++)
#pragma unroll
                for (int ni = 0; ni < 6; ni++)
                    mma_tf32(acc[mi][ni], af[mi], bf[ni]);
        }
        if (kc + 1 <= 53) storeA(smA + ((kc + 1) & 1) * ABUF_W);
    }

    // ---- epilogue: +bias, STG.64 ----
#pragma unroll
    for (int ni = 0; ni < 6; ni++) {
        int co = (wid & 3) * 48 + ni * 8 + (lane & 3) * 2;
        float bx = fb[co], by = fb[co + 1];
#pragma unroll
        for (int mi = 0; mi < 2; mi++) {
            int m0 = mt * 64 + (wm + mi) * 16 + (lane >> 2);
            size_t o0 = ((size_t)b * RR * RR + m0) * CC + co;
            *(float2*)(out + o0) =
                make_float2(acc[mi][ni][0] + bx, acc[mi][ni][1] + by);
            *(float2*)(out + o0 + (size_t)8 * CC) =
                make_float2(acc[mi][ni][2] + bx, acc[mi][ni][3] + by);
        }
    }
}

// ---------------------------------------------------------------------------
extern "C" void kernel_launch(void* const* d_in, const int* in_sizes, int n_in,
                              void* d_out, int out_size) {
    const float* x   = (const float*)d_in[0];
    const float* k1  = (const float*)d_in[1];
    const float* dcw = (const float*)d_in[2];
    const float* dcb = (const float*)d_in[3];
    const float* l1w = (const float*)d_in[4];
    const float* l1b = (const float*)d_in[5];
    const float* l2w = (const float*)d_in[6];
    const float* l2b = (const float*)d_in[7];
    const float* gkw = (const float*)d_in[8];
    const float* gkb = (const float*)d_in[9];
    const float* fw  = (const float*)d_in[10];
    const float* fb  = (const float*)d_in[11];
    float* out = (float*)d_out;

    cudaFuncSetAttribute(kD, cudaFuncAttributeMaxDynamicSharedMemorySize,
                         SMEM_WORDS * sizeof(float));

    kA<<<BB * WNN, CC>>>(x, k1, dcw, dcb);
    kB<<<1, 256>>>(l1w, l1b, l2w, l2b, gkw);
    kW<<<CC, CC>>>(k1, gkb, fw);
    dim3 g(RR, BB);   // 64 row-tiles x 4 batches = 256 CTAs
    kD<<<g, 256, SMEM_WORDS * sizeof(float)>>>(x, fb, out);
}

// round 6
// speedup vs baseline: 5.4928x; 1.1611x over previous
#include <cuda_runtime.h>
#include <math.h>
#include <cstdint>

#define BB   4
#define RR   64
#define CC   192
#define WNN  16
#define WSZ  16
#define TAPS 9

// ---------------- device scratch ----------------
__device__ float g_t[BB * WNN];
__device__ float g_w[BB * WNN];
__device__ float g_wg[BB * WNN];
// B operand in mma-fragment order: [b][tap][cg][6144 words]
__device__ float g_WeffB[BB * TAPS * 6 * 6144];

__device__ __forceinline__ uint32_t f2tf(float f) {
    uint32_t u; asm("cvt.rna.tf32.f32 %0, %1;" : "=r"(u) : "f"(f)); return u;
}
__device__ __forceinline__ void mma_tf32(float* d, const uint32_t* a, const uint32_t* b) {
    asm volatile(
        "mma.sync.aligned.m16n8k8.row.col.f32.tf32.tf32.f32 "
        "{%0,%1,%2,%3}, {%4,%5,%6,%7}, {%8,%9}, {%0,%1,%2,%3};"
        : "+f"(d[0]), "+f"(d[1]), "+f"(d[2]), "+f"(d[3])
        : "r"(a[0]), "r"(a[1]), "r"(a[2]), "r"(a[3]), "r"(b[0]), "r"(b[1]));
}

// ---------------------------------------------------------------------------
// Kernel A: pooled depthwise stats -> downchannel logits (validated)
// ---------------------------------------------------------------------------
__global__ void kA(const float* __restrict__ x, const float* __restrict__ k1,
                   const float* __restrict__ dcw, const float* __restrict__ dcb) {
    int b   = blockIdx.x >> 4;
    int win = blockIdx.x & 15;
    int c   = threadIdx.x;
    int rb  = win >> 2, cb = win & 3;
    const float* xp = x + ((size_t)b * RR * RR) * CC + c;
    int base = (rb * WSZ) * RR + cb * WSZ;

    float T = 0.f, r0 = 0.f, r15 = 0.f, c0 = 0.f, c15 = 0.f;
    float e00 = 0.f, e0f = 0.f, ef0 = 0.f, eff = 0.f;
    for (int i = 0; i < 16; i++) {
        float rowacc = 0.f, vj0 = 0.f, vj15 = 0.f;
#pragma unroll
        for (int j = 0; j < 16; j++) {
            float v = xp[(size_t)(base + i * RR + j) * CC];
            rowacc += v;
            if (j == 0)  { c0  += v; vj0  = v; }
            if (j == 15) { c15 += v; vj15 = v; }
        }
        T += rowacc;
        if (i == 0)  { r0  = rowacc; e00 = vj0; e0f = vj15; }
        if (i == 15) { r15 = rowacc; ef0 = vj0; eff = vj15; }
    }

    float Rex[3] = { r15, 0.f, r0 };
    float Cex[3] = { c15, 0.f, c0 };
    const float* kp = k1 + (size_t)(win * CC + c) * TAPS;
    float pooled = 0.f;
#pragma unroll
    for (int p = 0; p < 3; p++) {
#pragma unroll
        for (int q = 0; q < 3; q++) {
            float corner = 0.f;
            if (p == 0 && q == 0) corner = eff;
            if (p == 0 && q == 2) corner = ef0;
            if (p == 2 && q == 0) corner = e0f;
            if (p == 2 && q == 2) corner = e00;
            float S = T - Rex[p] - Cex[q] + corner;
            pooled += kp[p * 3 + q] * S;
        }
    }
    pooled *= (1.f / 256.f);
    float contrib = pooled * dcw[win * CC + c];

    __shared__ float red[192];
    red[c] = contrib;
    __syncthreads();
    for (int s = 96; s >= 6; s >>= 1) {
        if (c < s) red[c] += red[c + s];
        __syncthreads();
    }
    if (c == 0) {
        float tot = red[0] + red[1] + red[2] + red[3] + red[4] + red[5];
        g_t[b * WNN + win] = tot + dcb[win];
    }
}

// ---------------------------------------------------------------------------
// Kernel B: tiny MLP (validated)
// ---------------------------------------------------------------------------
__global__ void kB(const float* __restrict__ l1w, const float* __restrict__ l1b,
                   const float* __restrict__ l2w, const float* __restrict__ l2b,
                   const float* __restrict__ gkw) {
    __shared__ float ts[BB * WNN];
    __shared__ float hs[BB * 64];
    int tid = threadIdx.x;
    if (tid < BB * WNN) ts[tid] = g_t[tid];
    __syncthreads();
    {
        int b = tid >> 6, j = tid & 63;
        float a = l1b[j];
#pragma unroll
        for (int s = 0; s < 16; s++) a += ts[b * 16 + s] * l1w[j * 16 + s];
        hs[tid] = 0.5f * a * (1.f + erff(a * 0.70710678118654752f));
    }
    __syncthreads();
    if (tid < BB * WNN) {
        int b = tid >> 4, s = tid & 15;
        float a = l2b[s];
#pragma unroll
        for (int j = 0; j < 64; j++) a += hs[b * 64 + j] * l2w[s * 64 + j];
        float wv = 1.f / (1.f + expf(-a));
        g_w[tid]  = wv;
        g_wg[tid] = wv * gkw[s];
    }
}

// ---------------------------------------------------------------------------
// Kernel W: Weff in mma B-fragment order, tf32-pre-rounded (validated)
// word (per b,tap,cg chunk of 6144):
//   ((n>>3)*4 + (k32>>3))*64 + (n&7)*8 + (k32&3)*2 + ((k32>>2)&1)
// ---------------------------------------------------------------------------
__global__ void __launch_bounds__(192)
kW(const float* __restrict__ k1, const float* __restrict__ gkb,
   const float* __restrict__ fw) {
    int n = blockIdx.x;          // cout
    int c = threadIdx.x;         // cin = k
    __shared__ float sw_[64], swg[64];
    if (c < 64) { sw_[c] = g_w[c]; swg[c] = g_wg[c]; }
    __syncthreads();

    float f[17];
    const float* fp = fw + (size_t)n * ((WNN + 1) * CC) + c;
#pragma unroll
    for (int s = 0; s < 17; s++) f[s] = fp[s * CC];
    float g0 = gkb[0];

    int cg  = c >> 5, k32 = c & 31;
    int wrd = ((n >> 3) * 4 + (k32 >> 3)) * 64 + (n & 7) * 8 +
              (k32 & 3) * 2 + ((k32 >> 2) & 1);

#pragma unroll 1
    for (int tap = 0; tap < 9; tap++) {
        float kv[16];
#pragma unroll
        for (int s = 0; s < 16; s++)
            kv[s] = k1[((size_t)(s * CC + c)) * TAPS + tap];
#pragma unroll
        for (int b = 0; b < 4; b++) {
            float acc = 0.f, ga = g0;
#pragma unroll
            for (int s = 0; s < 16; s++) {
                acc = fmaf(sw_[b * 16 + s] * kv[s], f[s], acc);
                ga  = fmaf(swg[b * 16 + s], kv[s], ga);
            }
            acc = fmaf(ga, f[16], acc);
            g_WeffB[((size_t)(b * 9 + tap) * 6 + cg) * 6144 + wrd] =
                __uint_as_float(f2tf(acc));
        }
    }
}

// ---------------------------------------------------------------------------
// Kernel D: tf32 mma.sync implicit GEMM, 4 fat warps (64m x 48n each).
// CTA: M=64 (one image row) x N=192. K = 54 chunks of 32.
// A: gmem->reg->smem fragment-ordered, double buffered (16KB total).
// B: gmem->registers directly (fragment-ordered, coalesced), prefetch dist 1.
// ---------------------------------------------------------------------------
#define ABUF_W 2048

__global__ void __launch_bounds__(128, 2)
kD(const float* __restrict__ x, const float* __restrict__ fb,
   float* __restrict__ out) {
    __shared__ float smA[2][ABUF_W];

    int tid  = threadIdx.x;
    int lane = tid & 31;
    int wid  = tid >> 5;
    int b    = blockIdx.y;
    int mt   = blockIdx.x;           // image row, pixels [mt*64, mt*64+64)

    const float* xb = x + (size_t)b * RR * RR * CC;
    const float* WB = g_WeffB + (size_t)b * TAPS * 6 * 6144;
    int wn = wid * 6;                // warp's first n8-tile

    float acc[4][6][4];
#pragma unroll
    for (int mi = 0; mi < 4; mi++)
#pragma unroll
        for (int ni = 0; ni < 6; ni++)
#pragma unroll
            for (int r = 0; r < 4; r++) acc[mi][ni][r] = 0.f;

    float4   av[4];
    uint32_t bf[6][4][2];

    auto fetchA = [&](int kc) {
        int tap = kc / 6;
        int cbs = (kc - tap * 6) * 32;
        int dy = tap / 3 - 1, dx = tap % 3 - 1;
        int sy = mt + dy;
#pragma unroll
        for (int j = 0; j < 4; j++) {
            int i = tid + 128 * j;
            int m = i >> 3, f = i & 7;
            int sx = m + dx;
            if ((unsigned)sy < RR && (unsigned)sx < RR)
                av[j] = *(const float4*)(xb + ((size_t)(sy * RR + sx)) * CC + cbs + f * 4);
            else
                av[j] = make_float4(0.f, 0.f, 0.f, 0.f);
        }
    };
    auto storeA = [&](float* buf) {
#pragma unroll
        for (int j = 0; j < 4; j++) {
            int i = tid + 128 * j;
            int m = i >> 3, f = i & 7;
            int q  = ((m >> 4) << 2) + (f >> 1);
            int rb = ((f & 1) << 1) | ((m >> 3) & 1);
            float* p = buf + q * 128 + (m & 7) * 16 + rb;
            p[0]  = __uint_as_float(f2tf(av[j].x));
            p[4]  = __uint_as_float(f2tf(av[j].y));
            p[8]  = __uint_as_float(f2tf(av[j].z));
            p[12] = __uint_as_float(f2tf(av[j].w));
        }
    };
    auto loadB = [&](int kc) {
        int tap = kc / 6, cg = kc - tap * 6;
        const float* src = WB + ((size_t)tap * 6 + cg) * 6144;
#pragma unroll
        for (int ni = 0; ni < 6; ni++)
#pragma unroll
            for (int ks = 0; ks < 4; ks++) {
                float2 v = *(const float2*)(src + ((wn + ni) * 4 + ks) * 64 + lane * 2);
                bf[ni][ks][0] = __float_as_uint(v.x);
                bf[ni][ks][1] = __float_as_uint(v.y);
            }
    };

    // ---- prologue ----
    loadB(0);
    fetchA(0);
    storeA(smA[0]);
    __syncthreads();

#pragma unroll 1
    for (int kc = 0; kc < 54; kc++) {
        if (kc < 53) fetchA(kc + 1);        // long-latency LDG first

        const float* bufA = smA[kc & 1];
#pragma unroll
        for (int ks = 0; ks < 4; ks++) {
            uint32_t af[4][4];
#pragma unroll
            for (int mi = 0; mi < 4; mi++) {
                float4 v = *(const float4*)(bufA + (mi * 4 + ks) * 128 + lane * 4);
                af[mi][0] = __float_as_uint(v.x);
                af[mi][1] = __float_as_uint(v.y);
                af[mi][2] = __float_as_uint(v.z);
                af[mi][3] = __float_as_uint(v.w);
            }
#pragma unroll
            for (int mi = 0; mi < 4; mi++)
#pragma unroll
                for (int ni = 0; ni < 6; ni++)
                    mma_tf32(acc[mi][ni], af[mi], bf[ni][ks]);
        }

        if (kc < 53) {
            loadB(kc + 1);                  // refill B regs for next chunk
            storeA(smA[(kc + 1) & 1]);
        }
        __syncthreads();
    }

    // ---- epilogue: +bias, STG.64 ----
#pragma unroll
    for (int ni = 0; ni < 6; ni++) {
        int co = wid * 48 + ni * 8 + (lane & 3) * 2;
        float bx = fb[co], by = fb[co + 1];
#pragma unroll
        for (int mi = 0; mi < 4; mi++) {
            int m0 = mt * 64 + mi * 16 + (lane >> 2);
            size_t o0 = ((size_t)b * RR * RR + m0) * CC + co;
            *(float2*)(out + o0) =
                make_float2(acc[mi][ni][0] + bx, acc[mi][ni][1] + by);
            *(float2*)(out + o0 + (size_t)8 * CC) =
                make_float2(acc[mi][ni][2] + bx, acc[mi][ni][3] + by);
        }
    }
}

// ---------------------------------------------------------------------------
extern "C" void kernel_launch(void* const* d_in, const int* in_sizes, int n_in,
                              void* d_out, int out_size) {
    const float* x   = (const float*)d_in[0];
    const float* k1  = (const float*)d_in[1];
    const float* dcw = (const float*)d_in[2];
    const float* dcb = (const float*)d_in[3];
    const float* l1w = (const float*)d_in[4];
    const float* l1b = (const float*)d_in[5];
    const float* l2w = (const float*)d_in[6];
    const float* l2b = (const float*)d_in[7];
    const float* gkw = (const float*)d_in[8];
    const float* gkb = (const float*)d_in[9];
    const float* fw  = (const float*)d_in[10];
    const float* fb  = (const float*)d_in[11];
    float* out = (float*)d_out;

    kA<<<BB * WNN, CC>>>(x, k1, dcw, dcb);
    kB<<<1, 256>>>(l1w, l1b, l2w, l2b, gkw);
    kW<<<CC, CC>>>(k1, gkb, fw);
    dim3 g(RR, BB);   // 64 row-tiles x 4 batches = 256 CTAs
    kD<<<g, 128>>>(x, fb, out);
}